// round 1
// baseline (speedup 1.0000x reference)
#include <cuda_runtime.h>
#include <cstdint>

#define NS    128      // states
#define NA    32       // alphabet
#define NB    64       // batch
#define NT    4096     // time steps

// ---------------- device scratch (no allocations allowed) ----------------
__device__ float g_At[NS * NS];          // A transposed: g_At[j*NS + i] = A[i][j]
__device__ float g_Bm[NA * NS];          // emission probs [a][s]
__device__ float g_I[NS];                // initial dist
__device__ unsigned char g_tok[NB * NT]; // decoded tokens

// ---------------- packed f32x2 helpers ----------------
__device__ __forceinline__ void ffma2(unsigned long long& d,
                                      unsigned long long a,
                                      unsigned long long b) {
    asm("fma.rn.f32x2 %0, %1, %2, %3;" : "=l"(d) : "l"(a), "l"(b), "l"(d));
}
__device__ __forceinline__ unsigned long long add2(unsigned long long a,
                                                   unsigned long long b) {
    unsigned long long d;
    asm("add.rn.f32x2 %0, %1, %2;" : "=l"(d) : "l"(a), "l"(b));
    return d;
}
__device__ __forceinline__ void unpack2(float& lo, float& hi, unsigned long long v) {
    asm("mov.b64 {%0, %1}, %2;" : "=f"(lo), "=f"(hi) : "l"(v));
}

// ---------------- preprocessing: softmaxes ----------------
// one block, 128 threads; thread r handles row r of A, state-col r of B, elem r of I
__global__ void prep_params(const float* __restrict__ A_logits,
                            const float* __restrict__ B_logits,
                            const float* __restrict__ I_logits) {
    int r = threadIdx.x;

    // A: softmax over axis 1 (rows). Store transposed for column-register load.
    {
        float m = -1e30f;
        for (int c = 0; c < NS; c++) m = fmaxf(m, A_logits[r * NS + c]);
        float s = 0.f;
        for (int c = 0; c < NS; c++) s += expf(A_logits[r * NS + c] - m);
        float inv = 1.f / s;
        for (int c = 0; c < NS; c++)
            g_At[c * NS + r] = expf(A_logits[r * NS + c] - m) * inv;
    }
    // B: softmax over axis 0 (alphabet) per state column r
    {
        float m = -1e30f;
        for (int a = 0; a < NA; a++) m = fmaxf(m, B_logits[a * NS + r]);
        float s = 0.f;
        for (int a = 0; a < NA; a++) s += expf(B_logits[a * NS + r] - m);
        float inv = 1.f / s;
        for (int a = 0; a < NA; a++)
            g_Bm[a * NS + r] = expf(B_logits[a * NS + r] - m) * inv;
    }
    // I: softmax (redundant per-thread recompute, trivial cost)
    {
        float m = -1e30f;
        for (int i = 0; i < NS; i++) m = fmaxf(m, I_logits[i]);
        float s = 0.f;
        for (int i = 0; i < NS; i++) s += expf(I_logits[i] - m);
        g_I[r] = expf(I_logits[r] - m) / s;
    }
}

// ---------------- preprocessing: one-hot -> token ----------------
__global__ void prep_tokens(const float* __restrict__ inputs) {
    int n = blockIdx.x * blockDim.x + threadIdx.x;
    if (n >= NB * NT) return;
    const float4* p = (const float4*)(inputs + (size_t)n * NA);
    int tok = 0;
#pragma unroll
    for (int k = 0; k < 8; k++) {
        float4 v = p[k];
        if (v.x > 0.5f) tok = 4 * k;
        if (v.y > 0.5f) tok = 4 * k + 1;
        if (v.z > 0.5f) tok = 4 * k + 2;
        if (v.w > 0.5f) tok = 4 * k + 3;
    }
    g_tok[n] = (unsigned char)tok;
}

// ---------------- forward recurrence: 1 CTA per batch ----------------
__global__ void __launch_bounds__(128, 1) hmm_forward(float* __restrict__ out) {
    const int b = blockIdx.x;
    const int j = threadIdx.x;

    __shared__ float sB[NA * NS];                   // 16 KB emission table
    __shared__ __align__(16) unsigned char sTok[NT]; // 4 KB tokens
    __shared__ __align__(16) float sAlpha[2][NS];    // ping-pong alpha
    __shared__ float sPart[4];

    // stage emission table (coalesced)
#pragma unroll
    for (int k = 0; k < NA; k++) sB[k * NS + j] = g_Bm[k * NS + j];

    // stage tokens: 4096 B = 256 x int4
    {
        const int4* tg = (const int4*)(g_tok + (size_t)b * NT);
        int4* ts = (int4*)sTok;
        ts[j] = tg[j];
        ts[j + 128] = tg[j + 128];
    }

    // A column j into registers as packed f32x2 pairs (i, i+1)
    unsigned long long aR[64];
    {
        const ulonglong2* ap = (const ulonglong2*)(g_At + (size_t)j * NS);
#pragma unroll
        for (int k = 0; k < 32; k++) {
            ulonglong2 q = ap[k];
            aR[2 * k] = q.x;
            aR[2 * k + 1] = q.y;
        }
    }
    const float Ij = g_I[j];
    __syncthreads();

    double loglik = 0.0;

    // t = 0: alpha = I * E_0 (unnormalized; renorm cadence handles scaling)
    {
        int tok = sTok[0];
        sAlpha[0][j] = Ij * sB[tok * NS + j];
    }
    __syncthreads();

    for (int t = 1; t < NT; t++) {
        const ulonglong2* al = (const ulonglong2*)sAlpha[(t + 1) & 1];
        unsigned long long acc0 = 0ull, acc1 = 0ull, acc2 = 0ull, acc3 = 0ull;
#pragma unroll
        for (int k = 0; k < 32; k += 2) {
            ulonglong2 q0 = al[k];
            ffma2(acc0, q0.x, aR[2 * k]);
            ffma2(acc1, q0.y, aR[2 * k + 1]);
            ulonglong2 q1 = al[k + 1];
            ffma2(acc2, q1.x, aR[2 * k + 2]);
            ffma2(acc3, q1.y, aR[2 * k + 3]);
        }
        acc0 = add2(acc0, acc2);
        acc1 = add2(acc1, acc3);
        acc0 = add2(acc0, acc1);
        float lo, hi;
        unpack2(lo, hi, acc0);

        int tok = sTok[t];
        float v = (lo + hi) * sB[tok * NS + j];

        if ((t & 7) == 7) {  // renormalize every 8 steps (incl. final t=4095)
            float w = v;
#pragma unroll
            for (int off = 16; off > 0; off >>= 1)
                w += __shfl_xor_sync(0xffffffffu, w, off);
            if ((j & 31) == 0) sPart[j >> 5] = w;
            __syncthreads();
            float Ssum = (sPart[0] + sPart[1]) + (sPart[2] + sPart[3]);
            v *= __fdividef(1.0f, Ssum);
            loglik += (double)logf(Ssum);
        }

        sAlpha[t & 1][j] = v;
        __syncthreads();
    }

    if (j == 0) out[b] = (float)loglik;
}

// ---------------- launch ----------------
extern "C" void kernel_launch(void* const* d_in, const int* in_sizes, int n_in,
                              void* d_out, int out_size) {
    // identify inputs by element count (robust to ordering)
    const float* inputs = nullptr;   // 64*4096*32 = 8388608
    const float* A_logits = nullptr; // 128*128    = 16384
    const float* B_logits = nullptr; // 32*128     = 4096
    const float* I_logits = nullptr; // 128
    for (int i = 0; i < n_in; i++) {
        switch (in_sizes[i]) {
            case NB * NT * NA: inputs = (const float*)d_in[i]; break;
            case NS * NS:      A_logits = (const float*)d_in[i]; break;
            case NA * NS:      B_logits = (const float*)d_in[i]; break;
            case NS:           I_logits = (const float*)d_in[i]; break;
        }
    }
    float* out = (float*)d_out;

    prep_params<<<1, 128>>>(A_logits, B_logits, I_logits);
    prep_tokens<<<(NB * NT + 255) / 256, 256>>>(inputs);
    hmm_forward<<<NB, 128>>>(out);
}